// round 8
// baseline (speedup 1.0000x reference)
#include <cuda_runtime.h>
#include <math.h>

typedef unsigned long long u64;

#define BB 16
#define SS 4096
#define SP 4097
#define DD 1024
#define HH 16

// k2 persistent: 18 stripes x 16 b = 288 CTAs (2/SM), stripe 228 rows, 15 passes x 16
#define K2_NB     18
#define K2_STRIPE 228
#define K2_PASSES 15

// k4 persistent: 16 stripes x 16 b = 256 CTAs (2/SM), stripe 256 (last: 257)
#define K4_NB     16
#define K4_CH     128

// ---- scratch (no allocations allowed) ----
__device__ float g_q[BB * DD];
__device__ float g_qk[BB * HH * DD];
__device__ float g_scores[(size_t)BB * HH * SP];
__device__ float g_smax[BB * HH];
__device__ float g_sinv[BB * HH];
__device__ float g_upart[(size_t)BB * K4_NB * HH * DD];
__device__ float g_u[BB * HH * DD];
__device__ float g_ctx[BB * DD];

// ---- packed dual-fp32 helpers (sm_100+) ----
__device__ __forceinline__ u64 fma2(u64 a, u64 b, u64 c) {
    u64 d;
    asm("fma.rn.f32x2 %0, %1, %2, %3;" : "=l"(d) : "l"(a), "l"(b), "l"(c));
    return d;
}
__device__ __forceinline__ float hsum2(u64 v) {
    float lo, hi;
    asm("mov.b64 {%0, %1}, %2;" : "=f"(lo), "=f"(hi) : "l"(v));
    return lo + hi;
}

// K0: q[b,d] = 0.125 * (query[b,:] . w_in[d,:] + b_in[d])
__global__ void k0_qproj(const float* __restrict__ query,
                         const float* __restrict__ w_in,
                         const float* __restrict__ b_in) {
    int t = threadIdx.x;
    int b = t & 15;
    int d = blockIdx.x * 16 + (t >> 4);
    const float4* q = (const float4*)(query + b * DD);
    const float4* w = (const float4*)(w_in + (size_t)d * DD);
    float a0 = 0.f, a1 = 0.f, a2 = 0.f, a3 = 0.f;
#pragma unroll 8
    for (int j = 0; j < DD / 4; j++) {
        float4 qv = q[j], wv = w[j];
        a0 += qv.x * wv.x; a1 += qv.y * wv.y;
        a2 += qv.z * wv.z; a3 += qv.w * wv.w;
    }
    g_q[b * DD + d] = (a0 + a1 + a2 + a3 + b_in[d]) * 0.125f;
}

// K1: qk[b,h,j] = sum_i q[b, h*64+i] * w_in[DD + h*64+i, j]
__global__ void k1_qkfold(const float* __restrict__ w_in) {
    __shared__ float qsm[BB * 64];
    int h = blockIdx.x;
    int jc = blockIdx.y;
    int t = threadIdx.x;
    for (int idx = t; idx < BB * 64; idx += 256) {
        int b = idx >> 6, i = idx & 63;
        qsm[idx] = g_q[b * DD + h * 64 + i];
    }
    __syncthreads();
    int j = jc * 256 + t;
    float acc[BB];
#pragma unroll
    for (int b = 0; b < BB; b++) acc[b] = 0.f;
    const float* w = w_in + (size_t)(DD + h * 64) * DD + j;
#pragma unroll 4
    for (int i = 0; i < 64; i++) {
        float wv = w[(size_t)i * DD];
#pragma unroll
        for (int b = 0; b < BB; b++) acc[b] += qsm[b * 64 + i] * wv;
    }
#pragma unroll
    for (int b = 0; b < BB; b++) g_qk[(b * HH + h) * DD + j] = acc[b];
}

// K2: persistent fused key-copy + scores.
// Warp = (rq, hhalf): 4 rows x 8 heads per pass. Stores split: hhalf 0 -> rows 0,1;
// hhalf 1 -> rows 2,3. qk tile in smem loaded once per block.
__global__ void __launch_bounds__(256, 2)
k2_keyscores(const float* __restrict__ past_key,
             const float* __restrict__ key,
             float* __restrict__ comb_key) {
    extern __shared__ float qk_sm[];  // HH*DD floats = 64 KB
    int b = blockIdx.y;
    int t = threadIdx.x;
    {
        const float4* src = (const float4*)(g_qk + (size_t)b * HH * DD);
        float4* dst = (float4*)qk_sm;
        for (int i = t; i < HH * DD / 4; i += 256) dst[i] = src[i];
    }
    __syncthreads();

    int warp = t >> 5, lane = t & 31;
    int hhalf = warp & 1;
    int rq = warp >> 1;
    int h0 = hhalf * 8;
    int sb = blockIdx.x * K2_STRIPE;
    int send = sb + K2_STRIPE;
    if (send > SP) send = SP;
    int lj = lane * 4;

    for (int p = 0; p < K2_PASSES; p++) {
        int s0 = sb + p * 16 + rq * 4;   // warp-uniform
        if (s0 >= send) break;

        const float* src[4];
        bool v[4];
#pragma unroll
        for (int r = 0; r < 4; r++) {
            int s = s0 + r;
            v[r] = (s < send);
            int sc = v[r] ? s : (send - 1);
            src[r] = (sc < SS) ? past_key + ((size_t)b * SS + sc) * DD
                               : key + (size_t)b * DD;
        }
        float* dstb = comb_key + ((size_t)b * SP + s0) * DD;

        u64 acc[32];
#pragma unroll
        for (int i = 0; i < 32; i++) acc[i] = 0ull;

#pragma unroll
        for (int k = 0; k < 8; k++) {
            int jb = k * 128 + lj;
            ulonglong2 c[4];
#pragma unroll
            for (int r = 0; r < 4; r++) c[r] = *(const ulonglong2*)(src[r] + jb);

            // balanced stores: each hhalf stores 2 of the 4 rows
            int r0 = hhalf * 2;
            if (v[r0])     *(ulonglong2*)(dstb + (size_t)r0 * DD + jb) = c[r0];
            if (v[r0 + 1]) *(ulonglong2*)(dstb + (size_t)(r0 + 1) * DD + jb) = c[r0 + 1];

#pragma unroll
            for (int h8 = 0; h8 < 8; h8++) {
                ulonglong2 qv = *(const ulonglong2*)(qk_sm + (h0 + h8) * DD + jb);
#pragma unroll
                for (int r = 0; r < 4; r++) {
                    acc[h8 * 4 + r] = fma2(qv.x, c[r].x, acc[h8 * 4 + r]);
                    acc[h8 * 4 + r] = fma2(qv.y, c[r].y, acc[h8 * 4 + r]);
                }
            }
        }
#pragma unroll
        for (int i = 0; i < 32; i++) {
            float vv = hsum2(acc[i]);
            vv += __shfl_xor_sync(0xffffffffu, vv, 16);
            vv += __shfl_xor_sync(0xffffffffu, vv, 8);
            vv += __shfl_xor_sync(0xffffffffu, vv, 4);
            vv += __shfl_xor_sync(0xffffffffu, vv, 2);
            vv += __shfl_xor_sync(0xffffffffu, vv, 1);
            if (lane == 0) {
                int h8 = i >> 2, r = i & 3;
                if (v[r])
                    g_scores[((size_t)b * HH + h0 + h8) * SP + s0 + r] = vv;
            }
        }
    }
}

// K3: one-pass online softmax stats per row -> (max, 1/sum).
__global__ void k3_stats() {
    __shared__ float red_m[8], red_s[8];
    int row = blockIdx.x;
    const float* sc = g_scores + (size_t)row * SP;
    int t = threadIdx.x;

    float m = -1e30f, s = 0.f;
    for (int i = t; i < SP; i += 256) {
        float x = sc[i];
        float nm = fmaxf(m, x);
        s = s * __expf(m - nm) + __expf(x - nm);
        m = nm;
    }
#pragma unroll
    for (int o = 16; o; o >>= 1) {
        float om = __shfl_xor_sync(0xffffffffu, m, o);
        float os = __shfl_xor_sync(0xffffffffu, s, o);
        float nm = fmaxf(m, om);
        s = s * __expf(m - nm) + os * __expf(om - nm);
        m = nm;
    }
    if ((t & 31) == 0) { red_m[t >> 5] = m; red_s[t >> 5] = s; }
    __syncthreads();
    if (t == 0) {
        float M = red_m[0], S = red_s[0];
#pragma unroll
        for (int w = 1; w < 8; w++) {
            float nm = fmaxf(M, red_m[w]);
            S = S * __expf(M - nm) + red_s[w] * __expf(red_m[w] - nm);
            M = nm;
        }
        g_smax[row] = M;
        g_sinv[row] = 1.f / S;
    }
}

// K4: persistent fused value-copy + softmax-apply + u accumulation.
// 8-row iterations: 8 LDG.128 in flight per warp, loads a full iteration
// (~600 cyc of issue) ahead of their use. attn staged duplicated as
// float2{a,a} (zero-padded) so broadcast LDS.128 feeds fma2 directly.
__global__ void __launch_bounds__(256, 2)
k4_valu(const float* __restrict__ past_value,
        const float* __restrict__ value,
        float* __restrict__ comb_value) {
    __shared__ __align__(16) float2 attn2[HH][K4_CH];  // 16 KB
    int bx = blockIdx.x, b = blockIdx.y;
    int t = threadIdx.x;
    int j = t * 4;
    int sb = bx * 256;
    int rows_blk = SP - sb;
    if (rows_blk > 257) rows_blk = 256;   // blocks 0..14: 256, block 15: 257

    u64 acc[HH][2];
#pragma unroll
    for (int h = 0; h < HH; h++) { acc[h][0] = 0ull; acc[h][1] = 0ull; }

    for (int cs = 0; cs < rows_blk; cs += K4_CH) {
        int rows_c = rows_blk - cs;
        if (rows_c > K4_CH) rows_c = K4_CH;
        __syncthreads();
        for (int idx = t; idx < HH * K4_CH; idx += 256) {
            int h = idx >> 7, si = idx & (K4_CH - 1);
            float a = 0.f;
            if (si < rows_c) {
                float x = g_scores[((size_t)b * HH + h) * SP + sb + cs + si];
                a = __expf(x - g_smax[b * HH + h]) * g_sinv[b * HH + h];
            }
            attn2[h][si] = make_float2(a, a);
        }
        __syncthreads();

        int base = sb + cs;
        int n_it = (rows_c + 7) >> 3;

        for (int it = 0; it < n_it; it++) {
            int si0 = it * 8;
            ulonglong2 cur[8];
#pragma unroll
            for (int r = 0; r < 8; r++) {
                int s = base + si0 + r;
                if (s > SP - 1) s = SP - 1;
                const float* p = (s < SS) ? past_value + ((size_t)b * SS + s) * DD + j
                                          : value + (size_t)b * DD + j;
                cur[r] = *(const ulonglong2*)p;
            }
#pragma unroll
            for (int r = 0; r < 8; r++) {
                if (si0 + r < rows_c)
                    *(ulonglong2*)(comb_value + ((size_t)b * SP + base + si0 + r) * DD + j) = cur[r];
            }
#pragma unroll
            for (int h = 0; h < HH; h++) {
#pragma unroll
                for (int k = 0; k < 4; k++) {
                    ulonglong2 a2 = *(const ulonglong2*)(&attn2[h][si0 + 2 * k]);
                    acc[h][0] = fma2(a2.x, cur[2 * k].x, acc[h][0]);
                    acc[h][1] = fma2(a2.x, cur[2 * k].y, acc[h][1]);
                    acc[h][0] = fma2(a2.y, cur[2 * k + 1].x, acc[h][0]);
                    acc[h][1] = fma2(a2.y, cur[2 * k + 1].y, acc[h][1]);
                }
            }
        }
    }

    float* up = g_upart + ((size_t)(b * K4_NB + bx) * HH) * DD + j;
#pragma unroll
    for (int h = 0; h < HH; h++) {
        ulonglong2 o; o.x = acc[h][0]; o.y = acc[h][1];
        *(ulonglong2*)(up + (size_t)h * DD) = o;
    }
}

// K4b: u = sum over stripe-partials
__global__ void k4b_ured() {
    int idx = blockIdx.x * 256 + threadIdx.x;
    int e = idx * 4;
    int b = e >> 14;
    int rest = e & 16383;
    const float* up = g_upart + (size_t)b * K4_NB * HH * DD + rest;
    float4 s = make_float4(0.f, 0.f, 0.f, 0.f);
#pragma unroll
    for (int c = 0; c < K4_NB; c++) {
        float4 v = *(const float4*)(up + (size_t)c * HH * DD);
        s.x += v.x; s.y += v.y; s.z += v.z; s.w += v.w;
    }
    *(float4*)(g_u + e) = s;
}

// K5: ctx[b,d] = u[b, d>>6, :] . w_in[2D+d, :] + b_in[2D+d]
__global__ void k5_ctx(const float* __restrict__ w_in,
                       const float* __restrict__ b_in) {
    int t = threadIdx.x;
    int b = t & 15, d = blockIdx.x * 16 + (t >> 4);
    int h = d >> 6;
    const float4* u = (const float4*)(g_u + (b * HH + h) * DD);
    const float4* w = (const float4*)(w_in + (size_t)(2 * DD + d) * DD);
    float a0 = 0.f, a1 = 0.f, a2 = 0.f, a3 = 0.f;
#pragma unroll 8
    for (int jj = 0; jj < DD / 4; jj++) {
        float4 uv = u[jj], wv = w[jj];
        a0 += uv.x * wv.x; a1 += uv.y * wv.y;
        a2 += uv.z * wv.z; a3 += uv.w * wv.w;
    }
    g_ctx[b * DD + d] = a0 + a1 + a2 + a3 + b_in[2 * DD + d];
}

// K6: out[b,d] = ctx[b,:] . w_out[d,:] + b_out[d]
__global__ void k6_out(const float* __restrict__ w_out,
                       const float* __restrict__ b_out,
                       float* __restrict__ out) {
    int t = threadIdx.x;
    int b = t & 15, d = blockIdx.x * 16 + (t >> 4);
    const float4* c = (const float4*)(g_ctx + b * DD);
    const float4* w = (const float4*)(w_out + (size_t)d * DD);
    float a0 = 0.f, a1 = 0.f, a2 = 0.f, a3 = 0.f;
#pragma unroll 8
    for (int jj = 0; jj < DD / 4; jj++) {
        float4 cv = c[jj], wv = w[jj];
        a0 += cv.x * wv.x; a1 += cv.y * wv.y;
        a2 += cv.z * wv.z; a3 += cv.w * wv.w;
    }
    out[b * DD + d] = a0 + a1 + a2 + a3 + b_out[d];
}

extern "C" void kernel_launch(void* const* d_in, const int* in_sizes, int n_in,
                              void* d_out, int out_size) {
    const float* query      = (const float*)d_in[0];
    const float* key        = (const float*)d_in[1];
    const float* value      = (const float*)d_in[2];
    const float* past_key   = (const float*)d_in[3];
    const float* past_value = (const float*)d_in[4];
    const float* w_in       = (const float*)d_in[5];
    const float* b_in       = (const float*)d_in[6];
    const float* w_out      = (const float*)d_in[7];
    const float* b_out      = (const float*)d_in[8];

    float* out        = (float*)d_out;
    float* comb_key   = out + BB * DD;
    float* comb_value = comb_key + (size_t)BB * SP * DD;

    cudaFuncSetAttribute(k2_keyscores, cudaFuncAttributeMaxDynamicSharedMemorySize,
                         HH * DD * (int)sizeof(float));

    k0_qproj<<<64, 256>>>(query, w_in, b_in);
    k1_qkfold<<<dim3(16, 4), 256>>>(w_in);
    k2_keyscores<<<dim3(K2_NB, BB), 256, HH * DD * sizeof(float)>>>(past_key, key, comb_key);
    k3_stats<<<BB * HH, 256>>>();
    k4_valu<<<dim3(K4_NB, BB), 256>>>(past_value, value, comb_value);
    k4b_ured<<<256, 256>>>();
    k5_ctx<<<64, 256>>>(w_in, b_in);
    k6_out<<<64, 256>>>(w_out, b_out, out);
}

// round 10
// speedup vs baseline: 1.0803x; 1.0803x over previous
#include <cuda_runtime.h>
#include <math.h>

typedef unsigned long long u64;

#define BB 16
#define SS 4096
#define SP 4097
#define SPAD 4104              // padded scores row stride (multiple of 8 floats)
#define DD 1024
#define HH 16

// k2 persistent layout: 27 stripes x 16 batches = 432 CTAs (3 CTAs/SM @ 64KB smem)
#define K2_NB     27
#define K2_STRIPE 152
#define K2_ITERS  19           // 19 * 8 rows = 152

// k4 persistent layout: 18 stripes x 16 batches = 288 CTAs (2 CTAs/SM)
#define K4_NB     18
#define K4_STRIPE 228
#define K4_CH     128          // attn staging chunk

// ---- scratch (no allocations allowed) ----
__device__ float g_q[BB * DD];
__device__ float g_qk[BB * HH * DD];
__device__ __align__(16) float g_scores[(size_t)BB * HH * SPAD];
__device__ float g_smax[BB * HH];
__device__ float g_sinv[BB * HH];
__device__ float g_upart[(size_t)BB * K4_NB * HH * DD];
__device__ float g_u[BB * HH * DD];
__device__ float g_ctx[BB * DD];

// ---- packed dual-fp32 helpers (sm_100+) ----
__device__ __forceinline__ u64 fma2(u64 a, u64 b, u64 c) {
    u64 d;
    asm("fma.rn.f32x2 %0, %1, %2, %3;" : "=l"(d) : "l"(a), "l"(b), "l"(c));
    return d;
}
__device__ __forceinline__ float hsum2(u64 v) {
    float lo, hi;
    asm("mov.b64 {%0, %1}, %2;" : "=f"(lo), "=f"(hi) : "l"(v));
    return lo + hi;
}

// K0: q[b,d] = 0.125 * (query[b,:] . w_in[d,:] + b_in[d])
__global__ void k0_qproj(const float* __restrict__ query,
                         const float* __restrict__ w_in,
                         const float* __restrict__ b_in) {
    int t = threadIdx.x;
    int b = t & 15;
    int d = blockIdx.x * 16 + (t >> 4);
    const float4* q = (const float4*)(query + b * DD);
    const float4* w = (const float4*)(w_in + (size_t)d * DD);
    float a0 = 0.f, a1 = 0.f, a2 = 0.f, a3 = 0.f;
#pragma unroll 8
    for (int j = 0; j < DD / 4; j++) {
        float4 qv = q[j], wv = w[j];
        a0 += qv.x * wv.x; a1 += qv.y * wv.y;
        a2 += qv.z * wv.z; a3 += qv.w * wv.w;
    }
    g_q[b * DD + d] = (a0 + a1 + a2 + a3 + b_in[d]) * 0.125f;
}

// K1: qk[b,h,j] = sum_i q[b, h*64+i] * w_in[DD + h*64+i, j]
__global__ void k1_qkfold(const float* __restrict__ w_in) {
    __shared__ float qsm[BB * 64];
    int h = blockIdx.x;
    int jc = blockIdx.y;
    int t = threadIdx.x;
    for (int idx = t; idx < BB * 64; idx += 256) {
        int b = idx >> 6, i = idx & 63;
        qsm[idx] = g_q[b * DD + h * 64 + i];
    }
    __syncthreads();
    int j = jc * 256 + t;
    float acc[BB];
#pragma unroll
    for (int b = 0; b < BB; b++) acc[b] = 0.f;
    const float* w = w_in + (size_t)(DD + h * 64) * DD + j;
#pragma unroll 4
    for (int i = 0; i < 64; i++) {
        float wv = w[(size_t)i * DD];
#pragma unroll
        for (int b = 0; b < BB; b++) acc[b] += qsm[b * 64 + i] * wv;
    }
#pragma unroll
    for (int b = 0; b < BB; b++) g_qk[(b * HH + h) * DD + j] = acc[b];
}

// K2: persistent fused key-copy + scores, double-buffered k-loop.
// Stores balanced: hhalf 0 stores row s0, hhalf 1 stores row s0+1.
__global__ void __launch_bounds__(256, 3)
k2_keyscores(const float* __restrict__ past_key,
             const float* __restrict__ key,
             float* __restrict__ comb_key) {
    extern __shared__ float qk_sm[];  // HH*DD floats = 64 KB
    int b = blockIdx.y;
    int t = threadIdx.x;
    {
        const float4* src = (const float4*)(g_qk + (size_t)b * HH * DD);
        float4* dst = (float4*)qk_sm;
        for (int i = t; i < HH * DD / 4; i += 256) dst[i] = src[i];
    }
    __syncthreads();

    int warp = t >> 5, lane = t & 31;
    int hhalf = warp & 1;
    int rq = warp >> 1;
    int h0 = hhalf * 8;
    int stripe0 = blockIdx.x * K2_STRIPE;

    for (int it = 0; it < K2_ITERS; it++) {
        int s0 = stripe0 + it * 8 + rq * 2;   // warp-uniform
        if (s0 >= SP) break;
        bool valid1 = (s0 + 1) < SP;

        const float* src0 = (s0 < SS) ? past_key + ((size_t)b * SS + s0) * DD
                                      : key + (size_t)b * DD;
        const float* src1 = (s0 + 1 < SS) ? past_key + ((size_t)b * SS + s0 + 1) * DD
                                          : key + (size_t)b * DD;
        float* dst0 = comb_key + ((size_t)b * SP + s0) * DD;
        float* dst1 = comb_key + ((size_t)b * SP + (valid1 ? s0 + 1 : s0)) * DD;

        u64 acc[16];
#pragma unroll
        for (int i = 0; i < 16; i++) acc[i] = 0ull;

        int lj = lane * 4;
        ulonglong2 c0 = *(const ulonglong2*)(src0 + lj);
        ulonglong2 c1;
        if (valid1) c1 = *(const ulonglong2*)(src1 + lj);
        else { c1.x = 0ull; c1.y = 0ull; }

#pragma unroll
        for (int k = 0; k < 8; k++) {
            int jb = k * 128 + lj;
            ulonglong2 n0, n1;
            if (k < 7) {  // prefetch next chunk before compute
                n0 = *(const ulonglong2*)(src0 + jb + 128);
                if (valid1) n1 = *(const ulonglong2*)(src1 + jb + 128);
                else { n1.x = 0ull; n1.y = 0ull; }
            }
            // balanced stores: hhalf0 -> row s0, hhalf1 -> row s0+1
            if (hhalf == 0) {
                *(ulonglong2*)(dst0 + jb) = c0;
            } else if (valid1) {
                *(ulonglong2*)(dst1 + jb) = c1;
            }
#pragma unroll
            for (int h8 = 0; h8 < 8; h8++) {
                ulonglong2 qv = *(const ulonglong2*)(qk_sm + (h0 + h8) * DD + jb);
                acc[h8 * 2 + 0] = fma2(qv.x, c0.x, acc[h8 * 2 + 0]);
                acc[h8 * 2 + 0] = fma2(qv.y, c0.y, acc[h8 * 2 + 0]);
                acc[h8 * 2 + 1] = fma2(qv.x, c1.x, acc[h8 * 2 + 1]);
                acc[h8 * 2 + 1] = fma2(qv.y, c1.y, acc[h8 * 2 + 1]);
            }
            if (k < 7) { c0 = n0; c1 = n1; }
        }
#pragma unroll
        for (int i = 0; i < 16; i++) {
            float v = hsum2(acc[i]);
            v += __shfl_xor_sync(0xffffffffu, v, 16);
            v += __shfl_xor_sync(0xffffffffu, v, 8);
            v += __shfl_xor_sync(0xffffffffu, v, 4);
            v += __shfl_xor_sync(0xffffffffu, v, 2);
            v += __shfl_xor_sync(0xffffffffu, v, 1);
            if (lane == 0) {
                int h8 = i >> 1, r = i & 1;
                int s = s0 + r;
                if (s < SP)
                    g_scores[((size_t)b * HH + h0 + h8) * SPAD + s] = v;
            }
        }
    }
}

// K3: one-pass online softmax stats per row -> (max, 1/sum).
// float4 loads (SPAD-aligned rows), 4-wide max tree: chain 4 links not 16.
__global__ void k3_stats() {
    __shared__ float red_m[8], red_s[8];
    int row = blockIdx.x;
    const float* sc = g_scores + (size_t)row * SPAD;
    int t = threadIdx.x;

    float m = -1e30f, s = 0.f;
#pragma unroll
    for (int k = 0; k < 4; k++) {
        float4 x = *(const float4*)(sc + (k * 256 + t) * 4);
        float mx = fmaxf(fmaxf(x.x, x.y), fmaxf(x.z, x.w));
        float nm = fmaxf(m, mx);
        s = s * __expf(m - nm)
          + __expf(x.x - nm) + __expf(x.y - nm)
          + __expf(x.z - nm) + __expf(x.w - nm);
        m = nm;
    }
    if (t == 0) {  // tail element 4096
        float x = sc[4096];
        float nm = fmaxf(m, x);
        s = s * __expf(m - nm) + __expf(x - nm);
        m = nm;
    }
#pragma unroll
    for (int o = 16; o; o >>= 1) {
        float om = __shfl_xor_sync(0xffffffffu, m, o);
        float os = __shfl_xor_sync(0xffffffffu, s, o);
        float nm = fmaxf(m, om);
        s = s * __expf(m - nm) + os * __expf(om - nm);
        m = nm;
    }
    if ((t & 31) == 0) { red_m[t >> 5] = m; red_s[t >> 5] = s; }
    __syncthreads();
    if (t == 0) {
        float M = red_m[0], S = red_s[0];
#pragma unroll
        for (int w = 1; w < 8; w++) {
            float nm = fmaxf(M, red_m[w]);
            S = S * __expf(M - nm) + red_s[w] * __expf(red_m[w] - nm);
            M = nm;
        }
        g_smax[row] = M;
        g_sinv[row] = 1.f / S;
    }
}

// K4: persistent fused value-copy + softmax-apply + u accumulation.
// f32x2 over j-pairs; attn staged DUPLICATED (float2{a,a}); 4-row batches with
// register prefetch of the next batch (compute overlaps next loads).
__global__ void __launch_bounds__(256, 2)
k4_valu(const float* __restrict__ past_value,
        const float* __restrict__ value,
        float* __restrict__ comb_value) {
    __shared__ __align__(16) float2 attn2[HH][K4_CH];  // 16 KB
    int bx = blockIdx.x, b = blockIdx.y;
    int t = threadIdx.x;
    int j = t * 4;
    int s_begin = bx * K4_STRIPE;
    int rows_blk = SP - s_begin;
    if (rows_blk > K4_STRIPE) rows_blk = K4_STRIPE;

    u64 acc[HH][2];
#pragma unroll
    for (int h = 0; h < HH; h++) { acc[h][0] = 0ull; acc[h][1] = 0ull; }

    for (int cs = 0; cs < rows_blk; cs += K4_CH) {
        int rows_c = rows_blk - cs;
        if (rows_c > K4_CH) rows_c = K4_CH;
        __syncthreads();
        for (int idx = t; idx < HH * K4_CH; idx += 256) {
            int h = idx >> 7, si = idx & (K4_CH - 1);
            float a = 0.f;
            if (si < rows_c) {
                float x = g_scores[((size_t)b * HH + h) * SPAD + s_begin + cs + si];
                a = __expf(x - g_smax[b * HH + h]) * g_sinv[b * HH + h];
            }
            attn2[h][si] = make_float2(a, a);
        }
        __syncthreads();

        int base = s_begin + cs;
        int n_it = (rows_c + 3) >> 2;

        ulonglong2 cur[4];
#pragma unroll
        for (int r = 0; r < 4; r++) {
            int s = base + r; if (s > SP - 1) s = SP - 1;
            const float* p = (s < SS) ? past_value + ((size_t)b * SS + s) * DD + j
                                      : value + (size_t)b * DD + j;
            cur[r] = *(const ulonglong2*)p;
        }

        for (int it = 0; it < n_it; it++) {
            int si0 = it * 4;
            ulonglong2 nxt[4];
            if (it + 1 < n_it) {
#pragma unroll
                for (int r = 0; r < 4; r++) {
                    int s = base + si0 + 4 + r; if (s > SP - 1) s = SP - 1;
                    const float* p = (s < SS) ? past_value + ((size_t)b * SS + s) * DD + j
                                              : value + (size_t)b * DD + j;
                    nxt[r] = *(const ulonglong2*)p;
                }
            }
#pragma unroll
            for (int r = 0; r < 4; r++) {
                int s = base + si0 + r;
                if (s < SP && (si0 + r) < rows_c)
                    *(ulonglong2*)(comb_value + ((size_t)b * SP + s) * DD + j) = cur[r];
            }
#pragma unroll
            for (int h = 0; h < HH; h++) {
                ulonglong2 a01 = *(const ulonglong2*)(&attn2[h][si0]);
                ulonglong2 a23 = *(const ulonglong2*)(&attn2[h][si0 + 2]);
                acc[h][0] = fma2(a01.x, cur[0].x, acc[h][0]);
                acc[h][1] = fma2(a01.x, cur[0].y, acc[h][1]);
                acc[h][0] = fma2(a01.y, cur[1].x, acc[h][0]);
                acc[h][1] = fma2(a01.y, cur[1].y, acc[h][1]);
                acc[h][0] = fma2(a23.x, cur[2].x, acc[h][0]);
                acc[h][1] = fma2(a23.x, cur[2].y, acc[h][1]);
                acc[h][0] = fma2(a23.y, cur[3].x, acc[h][0]);
                acc[h][1] = fma2(a23.y, cur[3].y, acc[h][1]);
            }
            if (it + 1 < n_it) {
#pragma unroll
                for (int r = 0; r < 4; r++) cur[r] = nxt[r];
            }
        }
    }

    // lanes of acc are adjacent j's — store directly, no horizontal reduce
    float* up = g_upart + ((size_t)(b * K4_NB + bx) * HH) * DD + j;
#pragma unroll
    for (int h = 0; h < HH; h++) {
        ulonglong2 o; o.x = acc[h][0]; o.y = acc[h][1];
        *(ulonglong2*)(up + (size_t)h * DD) = o;
    }
}

// K4b: u = sum over stripe-partials
__global__ void k4b_ured() {
    int idx = blockIdx.x * 256 + threadIdx.x;
    int e = idx * 4;
    int b = e >> 14;
    int rest = e & 16383;
    const float* up = g_upart + (size_t)b * K4_NB * HH * DD + rest;
    float4 s = make_float4(0.f, 0.f, 0.f, 0.f);
#pragma unroll
    for (int c = 0; c < K4_NB; c++) {
        float4 v = *(const float4*)(up + (size_t)c * HH * DD);
        s.x += v.x; s.y += v.y; s.z += v.z; s.w += v.w;
    }
    *(float4*)(g_u + e) = s;
}

// K5: ctx[b,d] = u[b, d>>6, :] . w_in[2D+d, :] + b_in[2D+d]
__global__ void k5_ctx(const float* __restrict__ w_in,
                       const float* __restrict__ b_in) {
    int t = threadIdx.x;
    int b = t & 15, d = blockIdx.x * 16 + (t >> 4);
    int h = d >> 6;
    const float4* u = (const float4*)(g_u + (b * HH + h) * DD);
    const float4* w = (const float4*)(w_in + (size_t)(2 * DD + d) * DD);
    float a0 = 0.f, a1 = 0.f, a2 = 0.f, a3 = 0.f;
#pragma unroll 8
    for (int jj = 0; jj < DD / 4; jj++) {
        float4 uv = u[jj], wv = w[jj];
        a0 += uv.x * wv.x; a1 += uv.y * wv.y;
        a2 += uv.z * wv.z; a3 += uv.w * wv.w;
    }
    g_ctx[b * DD + d] = a0 + a1 + a2 + a3 + b_in[2 * DD + d];
}

// K6: out[b,d] = ctx[b,:] . w_out[d,:] + b_out[d]
__global__ void k6_out(const float* __restrict__ w_out,
                       const float* __restrict__ b_out,
                       float* __restrict__ out) {
    int t = threadIdx.x;
    int b = t & 15, d = blockIdx.x * 16 + (t >> 4);
    const float4* c = (const float4*)(g_ctx + b * DD);
    const float4* w = (const float4*)(w_out + (size_t)d * DD);
    float a0 = 0.f, a1 = 0.f, a2 = 0.f, a3 = 0.f;
#pragma unroll 8
    for (int jj = 0; jj < DD / 4; jj++) {
        float4 cv = c[jj], wv = w[jj];
        a0 += cv.x * wv.x; a1 += cv.y * wv.y;
        a2 += cv.z * wv.z; a3 += cv.w * wv.w;
    }
    out[b * DD + d] = a0 + a1 + a2 + a3 + b_out[d];
}

extern "C" void kernel_launch(void* const* d_in, const int* in_sizes, int n_in,
                              void* d_out, int out_size) {
    const float* query      = (const float*)d_in[0];
    const float* key        = (const float*)d_in[1];
    const float* value      = (const float*)d_in[2];
    const float* past_key   = (const float*)d_in[3];
    const float* past_value = (const float*)d_in[4];
    const float* w_in       = (const float*)d_in[5];
    const float* b_in       = (const float*)d_in[6];
    const float* w_out      = (const float*)d_in[7];
    const float* b_out      = (const float*)d_in[8];

    float* out        = (float*)d_out;
    float* comb_key   = out + BB * DD;
    float* comb_value = comb_key + (size_t)BB * SP * DD;

    cudaFuncSetAttribute(k2_keyscores, cudaFuncAttributeMaxDynamicSharedMemorySize,
                         HH * DD * (int)sizeof(float));

    k0_qproj<<<64, 256>>>(query, w_in, b_in);
    k1_qkfold<<<dim3(16, 4), 256>>>(w_in);
    k2_keyscores<<<dim3(K2_NB, BB), 256, HH * DD * sizeof(float)>>>(past_key, key, comb_key);
    k3_stats<<<BB * HH, 256>>>();
    k4_valu<<<dim3(K4_NB, BB), 256>>>(past_value, value, comb_value);
    k4b_ured<<<256, 256>>>();
    k5_ctx<<<64, 256>>>(w_in, b_in);
    k6_out<<<64, 256>>>(w_out, b_out, out);
}

// round 12
// speedup vs baseline: 1.3545x; 1.2538x over previous
#include <cuda_runtime.h>
#include <math.h>

typedef unsigned long long u64;

#define BB 16
#define SS 4096
#define SP 4097
#define SPAD 4104              // padded scores row stride (multiple of 8 floats)
#define DD 1024
#define HH 16

// k2 persistent layout: 27 stripes x 16 batches = 432 CTAs (3 CTAs/SM @ 64KB smem)
#define K2_NB     27
#define K2_STRIPE 152
#define K2_PASSES 19           // 19 * 8 rows = 152

// k4 persistent layout: 18 stripes x 16 batches = 288 CTAs (2 CTAs/SM)
#define K4_NB     18
#define K4_STRIPE 228
#define K4_CH     128          // attn staging chunk

// ---- scratch (no allocations allowed) ----
__device__ float g_q[BB * DD];
__device__ float g_qk[BB * HH * DD];
__device__ __align__(16) float g_scores[(size_t)BB * HH * SPAD];
__device__ float g_smax[BB * HH];
__device__ float g_sinv[BB * HH];
__device__ float g_upart[(size_t)BB * K4_NB * HH * DD];
__device__ float g_u[BB * HH * DD];
__device__ float g_ctx[BB * DD];

// ---- packed dual-fp32 helpers (sm_100+) ----
__device__ __forceinline__ u64 fma2(u64 a, u64 b, u64 c) {
    u64 d;
    asm("fma.rn.f32x2 %0, %1, %2, %3;" : "=l"(d) : "l"(a), "l"(b), "l"(c));
    return d;
}
__device__ __forceinline__ float hsum2(u64 v) {
    float lo, hi;
    asm("mov.b64 {%0, %1}, %2;" : "=f"(lo), "=f"(hi) : "l"(v));
    return lo + hi;
}

// K0: q[b,d] = 0.125 * (query[b,:] . w_in[d,:] + b_in[d])
__global__ void k0_qproj(const float* __restrict__ query,
                         const float* __restrict__ w_in,
                         const float* __restrict__ b_in) {
    int t = threadIdx.x;
    int b = t & 15;
    int d = blockIdx.x * 16 + (t >> 4);
    const float4* q = (const float4*)(query + b * DD);
    const float4* w = (const float4*)(w_in + (size_t)d * DD);
    float a0 = 0.f, a1 = 0.f, a2 = 0.f, a3 = 0.f;
#pragma unroll 8
    for (int j = 0; j < DD / 4; j++) {
        float4 qv = q[j], wv = w[j];
        a0 += qv.x * wv.x; a1 += qv.y * wv.y;
        a2 += qv.z * wv.z; a3 += qv.w * wv.w;
    }
    g_q[b * DD + d] = (a0 + a1 + a2 + a3 + b_in[d]) * 0.125f;
}

// K1: qk[b,h,j] = sum_i q[b, h*64+i] * w_in[DD + h*64+i, j]
__global__ void k1_qkfold(const float* __restrict__ w_in) {
    __shared__ float qsm[BB * 64];
    int h = blockIdx.x;
    int jc = blockIdx.y;
    int t = threadIdx.x;
    for (int idx = t; idx < BB * 64; idx += 256) {
        int b = idx >> 6, i = idx & 63;
        qsm[idx] = g_q[b * DD + h * 64 + i];
    }
    __syncthreads();
    int j = jc * 256 + t;
    float acc[BB];
#pragma unroll
    for (int b = 0; b < BB; b++) acc[b] = 0.f;
    const float* w = w_in + (size_t)(DD + h * 64) * DD + j;
#pragma unroll 4
    for (int i = 0; i < 64; i++) {
        float wv = w[(size_t)i * DD];
#pragma unroll
        for (int b = 0; b < BB; b++) acc[b] += qsm[b * 64 + i] * wv;
    }
#pragma unroll
    for (int b = 0; b < BB; b++) g_qk[(b * HH + h) * DD + j] = acc[b];
}

// K2: persistent fused key-copy + scores. WARP-OWNS-ROW:
// each warp reads one key row ONCE from global (no duplicate read),
// computes all 16 heads (acc[16] f32x2 = 32 regs), stores comb_key once.
// Double-buffered k-loop keeps the next 512B chunk in flight during compute.
__global__ void __launch_bounds__(256, 3)
k2_keyscores(const float* __restrict__ past_key,
             const float* __restrict__ key,
             float* __restrict__ comb_key) {
    extern __shared__ float qk_sm[];  // HH*DD floats = 64 KB
    int b = blockIdx.y;
    int t = threadIdx.x;
    {
        const float4* src = (const float4*)(g_qk + (size_t)b * HH * DD);
        float4* dst = (float4*)qk_sm;
        for (int i = t; i < HH * DD / 4; i += 256) dst[i] = src[i];
    }
    __syncthreads();

    int warp = t >> 5, lane = t & 31;
    int lj = lane * 4;
    int stripe0 = blockIdx.x * K2_STRIPE;

    for (int p = 0; p < K2_PASSES; p++) {
        int s = stripe0 + p * 8 + warp;   // warp-uniform row id
        if (s >= SP) break;               // only trailing warps exit early

        const float* src = (s < SS) ? past_key + ((size_t)b * SS + s) * DD
                                    : key + (size_t)b * DD;
        float* dst = comb_key + ((size_t)b * SP + s) * DD;

        u64 acc[HH];
#pragma unroll
        for (int i = 0; i < HH; i++) acc[i] = 0ull;

        ulonglong2 c = *(const ulonglong2*)(src + lj);
#pragma unroll
        for (int k = 0; k < 8; k++) {
            int jb = k * 128 + lj;
            ulonglong2 n;
            if (k < 7) n = *(const ulonglong2*)(src + jb + 128);  // prefetch
            *(ulonglong2*)(dst + jb) = c;
#pragma unroll
            for (int h = 0; h < HH; h++) {
                ulonglong2 qv = *(const ulonglong2*)(qk_sm + h * DD + jb);
                acc[h] = fma2(qv.x, c.x, acc[h]);
                acc[h] = fma2(qv.y, c.y, acc[h]);
            }
            if (k < 7) c = n;
        }
#pragma unroll
        for (int h = 0; h < HH; h++) {
            float v = hsum2(acc[h]);
            v += __shfl_xor_sync(0xffffffffu, v, 16);
            v += __shfl_xor_sync(0xffffffffu, v, 8);
            v += __shfl_xor_sync(0xffffffffu, v, 4);
            v += __shfl_xor_sync(0xffffffffu, v, 2);
            v += __shfl_xor_sync(0xffffffffu, v, 1);
            if (lane == 0)
                g_scores[((size_t)b * HH + h) * SPAD + s] = v;
        }
    }
}

// K3: one-pass online softmax stats per row -> (max, 1/sum).
// float4 loads (SPAD-aligned rows), 4-wide max tree: chain 4 links not 16.
__global__ void k3_stats() {
    __shared__ float red_m[8], red_s[8];
    int row = blockIdx.x;
    const float* sc = g_scores + (size_t)row * SPAD;
    int t = threadIdx.x;

    float m = -1e30f, s = 0.f;
#pragma unroll
    for (int k = 0; k < 4; k++) {
        float4 x = *(const float4*)(sc + (k * 256 + t) * 4);
        float mx = fmaxf(fmaxf(x.x, x.y), fmaxf(x.z, x.w));
        float nm = fmaxf(m, mx);
        s = s * __expf(m - nm)
          + __expf(x.x - nm) + __expf(x.y - nm)
          + __expf(x.z - nm) + __expf(x.w - nm);
        m = nm;
    }
    if (t == 0) {  // tail element 4096
        float x = sc[4096];
        float nm = fmaxf(m, x);
        s = s * __expf(m - nm) + __expf(x - nm);
        m = nm;
    }
#pragma unroll
    for (int o = 16; o; o >>= 1) {
        float om = __shfl_xor_sync(0xffffffffu, m, o);
        float os = __shfl_xor_sync(0xffffffffu, s, o);
        float nm = fmaxf(m, om);
        s = s * __expf(m - nm) + os * __expf(om - nm);
        m = nm;
    }
    if ((t & 31) == 0) { red_m[t >> 5] = m; red_s[t >> 5] = s; }
    __syncthreads();
    if (t == 0) {
        float M = red_m[0], S = red_s[0];
#pragma unroll
        for (int w = 1; w < 8; w++) {
            float nm = fmaxf(M, red_m[w]);
            S = S * __expf(M - nm) + red_s[w] * __expf(red_m[w] - nm);
            M = nm;
        }
        g_smax[row] = M;
        g_sinv[row] = 1.f / S;
    }
}

// K4: persistent fused value-copy + softmax-apply + u accumulation.
// f32x2 over j-pairs; attn staged DUPLICATED (float2{a,a}); 4-row batches with
// register prefetch of the next batch (compute overlaps next loads).
__global__ void __launch_bounds__(256, 2)
k4_valu(const float* __restrict__ past_value,
        const float* __restrict__ value,
        float* __restrict__ comb_value) {
    __shared__ __align__(16) float2 attn2[HH][K4_CH];  // 16 KB
    int bx = blockIdx.x, b = blockIdx.y;
    int t = threadIdx.x;
    int j = t * 4;
    int s_begin = bx * K4_STRIPE;
    int rows_blk = SP - s_begin;
    if (rows_blk > K4_STRIPE) rows_blk = K4_STRIPE;

    u64 acc[HH][2];
#pragma unroll
    for (int h = 0; h < HH; h++) { acc[h][0] = 0ull; acc[h][1] = 0ull; }

    for (int cs = 0; cs < rows_blk; cs += K4_CH) {
        int rows_c = rows_blk - cs;
        if (rows_c > K4_CH) rows_c = K4_CH;
        __syncthreads();
        for (int idx = t; idx < HH * K4_CH; idx += 256) {
            int h = idx >> 7, si = idx & (K4_CH - 1);
            float a = 0.f;
            if (si < rows_c) {
                float x = g_scores[((size_t)b * HH + h) * SPAD + s_begin + cs + si];
                a = __expf(x - g_smax[b * HH + h]) * g_sinv[b * HH + h];
            }
            attn2[h][si] = make_float2(a, a);
        }
        __syncthreads();

        int base = s_begin + cs;
        int n_it = (rows_c + 3) >> 2;

        ulonglong2 cur[4];
#pragma unroll
        for (int r = 0; r < 4; r++) {
            int s = base + r; if (s > SP - 1) s = SP - 1;
            const float* p = (s < SS) ? past_value + ((size_t)b * SS + s) * DD + j
                                      : value + (size_t)b * DD + j;
            cur[r] = *(const ulonglong2*)p;
        }

        for (int it = 0; it < n_it; it++) {
            int si0 = it * 4;
            ulonglong2 nxt[4];
            if (it + 1 < n_it) {
#pragma unroll
                for (int r = 0; r < 4; r++) {
                    int s = base + si0 + 4 + r; if (s > SP - 1) s = SP - 1;
                    const float* p = (s < SS) ? past_value + ((size_t)b * SS + s) * DD + j
                                              : value + (size_t)b * DD + j;
                    nxt[r] = *(const ulonglong2*)p;
                }
            }
#pragma unroll
            for (int r = 0; r < 4; r++) {
                int s = base + si0 + r;
                if (s < SP && (si0 + r) < rows_c)
                    *(ulonglong2*)(comb_value + ((size_t)b * SP + s) * DD + j) = cur[r];
            }
#pragma unroll
            for (int h = 0; h < HH; h++) {
                ulonglong2 a01 = *(const ulonglong2*)(&attn2[h][si0]);
                ulonglong2 a23 = *(const ulonglong2*)(&attn2[h][si0 + 2]);
                acc[h][0] = fma2(a01.x, cur[0].x, acc[h][0]);
                acc[h][1] = fma2(a01.x, cur[0].y, acc[h][1]);
                acc[h][0] = fma2(a01.y, cur[1].x, acc[h][0]);
                acc[h][1] = fma2(a01.y, cur[1].y, acc[h][1]);
                acc[h][0] = fma2(a23.x, cur[2].x, acc[h][0]);
                acc[h][1] = fma2(a23.x, cur[2].y, acc[h][1]);
                acc[h][0] = fma2(a23.y, cur[3].x, acc[h][0]);
                acc[h][1] = fma2(a23.y, cur[3].y, acc[h][1]);
            }
            if (it + 1 < n_it) {
#pragma unroll
                for (int r = 0; r < 4; r++) cur[r] = nxt[r];
            }
        }
    }

    // lanes of acc are adjacent j's — store directly, no horizontal reduce
    float* up = g_upart + ((size_t)(b * K4_NB + bx) * HH) * DD + j;
#pragma unroll
    for (int h = 0; h < HH; h++) {
        ulonglong2 o; o.x = acc[h][0]; o.y = acc[h][1];
        *(ulonglong2*)(up + (size_t)h * DD) = o;
    }
}

// K4b: u = sum over stripe-partials
__global__ void k4b_ured() {
    int idx = blockIdx.x * 256 + threadIdx.x;
    int e = idx * 4;
    int b = e >> 14;
    int rest = e & 16383;
    const float* up = g_upart + (size_t)b * K4_NB * HH * DD + rest;
    float4 s = make_float4(0.f, 0.f, 0.f, 0.f);
#pragma unroll
    for (int c = 0; c < K4_NB; c++) {
        float4 v = *(const float4*)(up + (size_t)c * HH * DD);
        s.x += v.x; s.y += v.y; s.z += v.z; s.w += v.w;
    }
    *(float4*)(g_u + e) = s;
}

// K5: ctx[b,d] = u[b, d>>6, :] . w_in[2D+d, :] + b_in[2D+d]
__global__ void k5_ctx(const float* __restrict__ w_in,
                       const float* __restrict__ b_in) {
    int t = threadIdx.x;
    int b = t & 15, d = blockIdx.x * 16 + (t >> 4);
    int h = d >> 6;
    const float4* u = (const float4*)(g_u + (b * HH + h) * DD);
    const float4* w = (const float4*)(w_in + (size_t)(2 * DD + d) * DD);
    float a0 = 0.f, a1 = 0.f, a2 = 0.f, a3 = 0.f;
#pragma unroll 8
    for (int jj = 0; jj < DD / 4; jj++) {
        float4 uv = u[jj], wv = w[jj];
        a0 += uv.x * wv.x; a1 += uv.y * wv.y;
        a2 += uv.z * wv.z; a3 += uv.w * wv.w;
    }
    g_ctx[b * DD + d] = a0 + a1 + a2 + a3 + b_in[2 * DD + d];
}

// K6: out[b,d] = ctx[b,:] . w_out[d,:] + b_out[d]
__global__ void k6_out(const float* __restrict__ w_out,
                       const float* __restrict__ b_out,
                       float* __restrict__ out) {
    int t = threadIdx.x;
    int b = t & 15, d = blockIdx.x * 16 + (t >> 4);
    const float4* c = (const float4*)(g_ctx + b * DD);
    const float4* w = (const float4*)(w_out + (size_t)d * DD);
    float a0 = 0.f, a1 = 0.f, a2 = 0.f, a3 = 0.f;
#pragma unroll 8
    for (int jj = 0; jj < DD / 4; jj++) {
        float4 cv = c[jj], wv = w[jj];
        a0 += cv.x * wv.x; a1 += cv.y * wv.y;
        a2 += cv.z * wv.z; a3 += cv.w * wv.w;
    }
    out[b * DD + d] = a0 + a1 + a2 + a3 + b_out[d];
}

extern "C" void kernel_launch(void* const* d_in, const int* in_sizes, int n_in,
                              void* d_out, int out_size) {
    const float* query      = (const float*)d_in[0];
    const float* key        = (const float*)d_in[1];
    const float* value      = (const float*)d_in[2];
    const float* past_key   = (const float*)d_in[3];
    const float* past_value = (const float*)d_in[4];
    const float* w_in       = (const float*)d_in[5];
    const float* b_in       = (const float*)d_in[6];
    const float* w_out      = (const float*)d_in[7];
    const float* b_out      = (const float*)d_in[8];

    float* out        = (float*)d_out;
    float* comb_key   = out + BB * DD;
    float* comb_value = comb_key + (size_t)BB * SP * DD;

    cudaFuncSetAttribute(k2_keyscores, cudaFuncAttributeMaxDynamicSharedMemorySize,
                         HH * DD * (int)sizeof(float));

    k0_qproj<<<64, 256>>>(query, w_in, b_in);
    k1_qkfold<<<dim3(16, 4), 256>>>(w_in);
    k2_keyscores<<<dim3(K2_NB, BB), 256, HH * DD * sizeof(float)>>>(past_key, key, comb_key);
    k3_stats<<<BB * HH, 256>>>();
    k4_valu<<<dim3(K4_NB, BB), 256>>>(past_value, value, comb_value);
    k4b_ured<<<256, 256>>>();
    k5_ctx<<<64, 256>>>(w_in, b_in);
    k6_out<<<64, 256>>>(w_out, b_out, out);
}

// round 15
// speedup vs baseline: 1.4285x; 1.0546x over previous
#include <cuda_runtime.h>
#include <math.h>

typedef unsigned long long u64;

#define BB 16
#define SS 4096
#define SP 4097
#define SPAD 4104              // padded scores row stride (multiple of 8 floats)
#define DD 1024
#define HH 16

// k2 persistent: 18 stripes x 16 b = 288 CTAs (2/SM @ 64KB smem, ~100 regs)
#define K2_NB     18
#define K2_STRIPE 228
#define K2_PASSES 15           // 15 * 16 rows = 240 >= 228

// k4 persistent layout: 18 stripes x 16 batches = 288 CTAs (2 CTAs/SM)
#define K4_NB     18
#define K4_STRIPE 228
#define K4_CH     128          // attn staging chunk

// ---- scratch (no allocations allowed) ----
__device__ float g_q[BB * DD];
__device__ float g_qk[BB * HH * DD];
__device__ __align__(16) float g_scores[(size_t)BB * HH * SPAD];
__device__ float g_smax[BB * HH];
__device__ float g_sinv[BB * HH];
__device__ float g_upart[(size_t)BB * K4_NB * HH * DD];
__device__ float g_u[BB * HH * DD];
__device__ float g_ctx[BB * DD];

// ---- packed dual-fp32 helpers (sm_100+) ----
__device__ __forceinline__ u64 fma2(u64 a, u64 b, u64 c) {
    u64 d;
    asm("fma.rn.f32x2 %0, %1, %2, %3;" : "=l"(d) : "l"(a), "l"(b), "l"(c));
    return d;
}
__device__ __forceinline__ float hsum2(u64 v) {
    float lo, hi;
    asm("mov.b64 {%0, %1}, %2;" : "=f"(lo), "=f"(hi) : "l"(v));
    return lo + hi;
}

// K0: q[b,d] = 0.125 * (query[b,:] . w_in[d,:] + b_in[d])
__global__ void k0_qproj(const float* __restrict__ query,
                         const float* __restrict__ w_in,
                         const float* __restrict__ b_in) {
    int t = threadIdx.x;
    int b = t & 15;
    int d = blockIdx.x * 16 + (t >> 4);
    const float4* q = (const float4*)(query + b * DD);
    const float4* w = (const float4*)(w_in + (size_t)d * DD);
    float a0 = 0.f, a1 = 0.f, a2 = 0.f, a3 = 0.f;
#pragma unroll 8
    for (int j = 0; j < DD / 4; j++) {
        float4 qv = q[j], wv = w[j];
        a0 += qv.x * wv.x; a1 += qv.y * wv.y;
        a2 += qv.z * wv.z; a3 += qv.w * wv.w;
    }
    g_q[b * DD + d] = (a0 + a1 + a2 + a3 + b_in[d]) * 0.125f;
}

// K1: qk[b,h,j] = sum_i q[b, h*64+i] * w_in[DD + h*64+i, j]
__global__ void k1_qkfold(const float* __restrict__ w_in) {
    __shared__ float qsm[BB * 64];
    int h = blockIdx.x;
    int jc = blockIdx.y;
    int t = threadIdx.x;
    for (int idx = t; idx < BB * 64; idx += 256) {
        int b = idx >> 6, i = idx & 63;
        qsm[idx] = g_q[b * DD + h * 64 + i];
    }
    __syncthreads();
    int j = jc * 256 + t;
    float acc[BB];
#pragma unroll
    for (int b = 0; b < BB; b++) acc[b] = 0.f;
    const float* w = w_in + (size_t)(DD + h * 64) * DD + j;
#pragma unroll 4
    for (int i = 0; i < 64; i++) {
        float wv = w[(size_t)i * DD];
#pragma unroll
        for (int b = 0; b < BB; b++) acc[b] += qsm[b * 64 + i] * wv;
    }
#pragma unroll
    for (int b = 0; b < BB; b++) g_qk[(b * HH + h) * DD + j] = acc[b];
}

// K2: persistent fused key-copy + scores. Warp = (rq, hhalf):
// 4 rows x 8 heads per warp -> qk smem traffic is 16KB per 4KB key row
// (vs 32KB at 2 rows, 64KB at 1 row) — crossbar no longer the binder.
// The 2nd read of each row by the other hhalf warp hits L2 (same CTA, same time).
// Stores balanced: hhalf0 stores rows 0-1, hhalf1 stores rows 2-3.
__global__ void __launch_bounds__(256, 2)
k2_keyscores(const float* __restrict__ past_key,
             const float* __restrict__ key,
             float* __restrict__ comb_key) {
    extern __shared__ float qk_sm[];  // HH*DD floats = 64 KB
    int b = blockIdx.y;
    int t = threadIdx.x;
    {
        const float4* src = (const float4*)(g_qk + (size_t)b * HH * DD);
        float4* dst = (float4*)qk_sm;
        for (int i = t; i < HH * DD / 4; i += 256) dst[i] = src[i];
    }
    __syncthreads();

    int warp = t >> 5, lane = t & 31;
    int hhalf = warp & 1;
    int rq = warp >> 1;
    int h0 = hhalf * 8;
    int sb = blockIdx.x * K2_STRIPE;
    int send = sb + K2_STRIPE;
    if (send > SP) send = SP;
    int lj = lane * 4;

    for (int p = 0; p < K2_PASSES; p++) {
        int s0 = sb + p * 16 + rq * 4;   // warp-uniform
        if (s0 >= send) break;

        const float* src[4];
        bool v[4];
#pragma unroll
        for (int r = 0; r < 4; r++) {
            int s = s0 + r;
            v[r] = (s < send);
            int sc = v[r] ? s : (send - 1);
            src[r] = (sc < SS) ? past_key + ((size_t)b * SS + sc) * DD
                               : key + (size_t)b * DD;
        }
        float* dstb = comb_key + ((size_t)b * SP + s0) * DD;

        u64 acc[32];
#pragma unroll
        for (int i = 0; i < 32; i++) acc[i] = 0ull;

#pragma unroll
        for (int k = 0; k < 8; k++) {
            int jb = k * 128 + lj;
            ulonglong2 c[4];
#pragma unroll
            for (int r = 0; r < 4; r++) c[r] = *(const ulonglong2*)(src[r] + jb);

            // balanced stores: each hhalf stores 2 of the 4 rows
            int r0 = hhalf * 2;
            if (v[r0])     *(ulonglong2*)(dstb + (size_t)r0 * DD + jb) = c[r0];
            if (v[r0 + 1]) *(ulonglong2*)(dstb + (size_t)(r0 + 1) * DD + jb) = c[r0 + 1];

#pragma unroll
            for (int h8 = 0; h8 < 8; h8++) {
                ulonglong2 qv = *(const ulonglong2*)(qk_sm + (h0 + h8) * DD + jb);
#pragma unroll
                for (int r = 0; r < 4; r++) {
                    acc[h8 * 4 + r] = fma2(qv.x, c[r].x, acc[h8 * 4 + r]);
                    acc[h8 * 4 + r] = fma2(qv.y, c[r].y, acc[h8 * 4 + r]);
                }
            }
        }
#pragma unroll
        for (int i = 0; i < 32; i++) {
            float vv = hsum2(acc[i]);
            vv += __shfl_xor_sync(0xffffffffu, vv, 16);
            vv += __shfl_xor_sync(0xffffffffu, vv, 8);
            vv += __shfl_xor_sync(0xffffffffu, vv, 4);
            vv += __shfl_xor_sync(0xffffffffu, vv, 2);
            vv += __shfl_xor_sync(0xffffffffu, vv, 1);
            if (lane == 0) {
                int h8 = i >> 2, r = i & 3;
                if (v[r])
                    g_scores[((size_t)b * HH + h0 + h8) * SPAD + s0 + r] = vv;
            }
        }
    }
}

// K3: one-pass online softmax stats per row -> (max, 1/sum).
// float4 loads (SPAD-aligned rows), 4-wide max tree: chain 4 links not 16.
__global__ void k3_stats() {
    __shared__ float red_m[8], red_s[8];
    int row = blockIdx.x;
    const float* sc = g_scores + (size_t)row * SPAD;
    int t = threadIdx.x;

    float m = -1e30f, s = 0.f;
#pragma unroll
    for (int k = 0; k < 4; k++) {
        float4 x = *(const float4*)(sc + (k * 256 + t) * 4);
        float mx = fmaxf(fmaxf(x.x, x.y), fmaxf(x.z, x.w));
        float nm = fmaxf(m, mx);
        s = s * __expf(m - nm)
          + __expf(x.x - nm) + __expf(x.y - nm)
          + __expf(x.z - nm) + __expf(x.w - nm);
        m = nm;
    }
    if (t == 0) {  // tail element 4096
        float x = sc[4096];
        float nm = fmaxf(m, x);
        s = s * __expf(m - nm) + __expf(x - nm);
        m = nm;
    }
#pragma unroll
    for (int o = 16; o; o >>= 1) {
        float om = __shfl_xor_sync(0xffffffffu, m, o);
        float os = __shfl_xor_sync(0xffffffffu, s, o);
        float nm = fmaxf(m, om);
        s = s * __expf(m - nm) + os * __expf(om - nm);
        m = nm;
    }
    if ((t & 31) == 0) { red_m[t >> 5] = m; red_s[t >> 5] = s; }
    __syncthreads();
    if (t == 0) {
        float M = red_m[0], S = red_s[0];
#pragma unroll
        for (int w = 1; w < 8; w++) {
            float nm = fmaxf(M, red_m[w]);
            S = S * __expf(M - nm) + red_s[w] * __expf(red_m[w] - nm);
            M = nm;
        }
        g_smax[row] = M;
        g_sinv[row] = 1.f / S;
    }
}

// K4: persistent fused value-copy + softmax-apply + u accumulation.
// f32x2 over j-pairs; attn staged DUPLICATED (float2{a,a}); 4-row batches with
// register prefetch of the next batch (compute overlaps next loads).
__global__ void __launch_bounds__(256, 2)
k4_valu(const float* __restrict__ past_value,
        const float* __restrict__ value,
        float* __restrict__ comb_value) {
    __shared__ __align__(16) float2 attn2[HH][K4_CH];  // 16 KB
    int bx = blockIdx.x, b = blockIdx.y;
    int t = threadIdx.x;
    int j = t * 4;
    int s_begin = bx * K4_STRIPE;
    int rows_blk = SP - s_begin;
    if (rows_blk > K4_STRIPE) rows_blk = K4_STRIPE;

    u64 acc[HH][2];
#pragma unroll
    for (int h = 0; h < HH; h++) { acc[h][0] = 0ull; acc[h][1] = 0ull; }

    for (int cs = 0; cs < rows_blk; cs += K4_CH) {
        int rows_c = rows_blk - cs;
        if (rows_c > K4_CH) rows_c = K4_CH;
        __syncthreads();
        for (int idx = t; idx < HH * K4_CH; idx += 256) {
            int h = idx >> 7, si = idx & (K4_CH - 1);
            float a = 0.f;
            if (si < rows_c) {
                float x = g_scores[((size_t)b * HH + h) * SPAD + s_begin + cs + si];
                a = __expf(x - g_smax[b * HH + h]) * g_sinv[b * HH + h];
            }
            attn2[h][si] = make_float2(a, a);
        }
        __syncthreads();

        int base = s_begin + cs;
        int n_it = (rows_c + 3) >> 2;

        ulonglong2 cur[4];
#pragma unroll
        for (int r = 0; r < 4; r++) {
            int s = base + r; if (s > SP - 1) s = SP - 1;
            const float* p = (s < SS) ? past_value + ((size_t)b * SS + s) * DD + j
                                      : value + (size_t)b * DD + j;
            cur[r] = *(const ulonglong2*)p;
        }

        for (int it = 0; it < n_it; it++) {
            int si0 = it * 4;
            ulonglong2 nxt[4];
            if (it + 1 < n_it) {
#pragma unroll
                for (int r = 0; r < 4; r++) {
                    int s = base + si0 + 4 + r; if (s > SP - 1) s = SP - 1;
                    const float* p = (s < SS) ? past_value + ((size_t)b * SS + s) * DD + j
                                              : value + (size_t)b * DD + j;
                    nxt[r] = *(const ulonglong2*)p;
                }
            }
#pragma unroll
            for (int r = 0; r < 4; r++) {
                int s = base + si0 + r;
                if (s < SP && (si0 + r) < rows_c)
                    *(ulonglong2*)(comb_value + ((size_t)b * SP + s) * DD + j) = cur[r];
            }
#pragma unroll
            for (int h = 0; h < HH; h++) {
                ulonglong2 a01 = *(const ulonglong2*)(&attn2[h][si0]);
                ulonglong2 a23 = *(const ulonglong2*)(&attn2[h][si0 + 2]);
                acc[h][0] = fma2(a01.x, cur[0].x, acc[h][0]);
                acc[h][1] = fma2(a01.x, cur[0].y, acc[h][1]);
                acc[h][0] = fma2(a01.y, cur[1].x, acc[h][0]);
                acc[h][1] = fma2(a01.y, cur[1].y, acc[h][1]);
                acc[h][0] = fma2(a23.x, cur[2].x, acc[h][0]);
                acc[h][1] = fma2(a23.x, cur[2].y, acc[h][1]);
                acc[h][0] = fma2(a23.y, cur[3].x, acc[h][0]);
                acc[h][1] = fma2(a23.y, cur[3].y, acc[h][1]);
            }
            if (it + 1 < n_it) {
#pragma unroll
                for (int r = 0; r < 4; r++) cur[r] = nxt[r];
            }
        }
    }

    // lanes of acc are adjacent j's — store directly, no horizontal reduce
    float* up = g_upart + ((size_t)(b * K4_NB + bx) * HH) * DD + j;
#pragma unroll
    for (int h = 0; h < HH; h++) {
        ulonglong2 o; o.x = acc[h][0]; o.y = acc[h][1];
        *(ulonglong2*)(up + (size_t)h * DD) = o;
    }
}

// K4b: u = sum over stripe-partials
__global__ void k4b_ured() {
    int idx = blockIdx.x * 256 + threadIdx.x;
    int e = idx * 4;
    int b = e >> 14;
    int rest = e & 16383;
    const float* up = g_upart + (size_t)b * K4_NB * HH * DD + rest;
    float4 s = make_float4(0.f, 0.f, 0.f, 0.f);
#pragma unroll
    for (int c = 0; c < K4_NB; c++) {
        float4 v = *(const float4*)(up + (size_t)c * HH * DD);
        s.x += v.x; s.y += v.y; s.z += v.z; s.w += v.w;
    }
    *(float4*)(g_u + e) = s;
}

// K5: ctx[b,d] = u[b, d>>6, :] . w_in[2D+d, :] + b_in[2D+d]
__global__ void k5_ctx(const float* __restrict__ w_in,
                       const float* __restrict__ b_in) {
    int t = threadIdx.x;
    int b = t & 15, d = blockIdx.x * 16 + (t >> 4);
    int h = d >> 6;
    const float4* u = (const float4*)(g_u + (b * HH + h) * DD);
    const float4* w = (const float4*)(w_in + (size_t)(2 * DD + d) * DD);
    float a0 = 0.f, a1 = 0.f, a2 = 0.f, a3 = 0.f;
#pragma unroll 8
    for (int jj = 0; jj < DD / 4; jj++) {
        float4 uv = u[jj], wv = w[jj];
        a0 += uv.x * wv.x; a1 += uv.y * wv.y;
        a2 += uv.z * wv.z; a3 += uv.w * wv.w;
    }
    g_ctx[b * DD + d] = a0 + a1 + a2 + a3 + b_in[2 * DD + d];
}

// K6: out[b,d] = ctx[b,:] . w_out[d,:] + b_out[d]
__global__ void k6_out(const float* __restrict__ w_out,
                       const float* __restrict__ b_out,
                       float* __restrict__ out) {
    int t = threadIdx.x;
    int b = t & 15, d = blockIdx.x * 16 + (t >> 4);
    const float4* c = (const float4*)(g_ctx + b * DD);
    const float4* w = (const float4*)(w_out + (size_t)d * DD);
    float a0 = 0.f, a1 = 0.f, a2 = 0.f, a3 = 0.f;
#pragma unroll 8
    for (int jj = 0; jj < DD / 4; jj++) {
        float4 cv = c[jj], wv = w[jj];
        a0 += cv.x * wv.x; a1 += cv.y * wv.y;
        a2 += cv.z * wv.z; a3 += cv.w * wv.w;
    }
    out[b * DD + d] = a0 + a1 + a2 + a3 + b_out[d];
}

extern "C" void kernel_launch(void* const* d_in, const int* in_sizes, int n_in,
                              void* d_out, int out_size) {
    const float* query      = (const float*)d_in[0];
    const float* key        = (const float*)d_in[1];
    const float* value      = (const float*)d_in[2];
    const float* past_key   = (const float*)d_in[3];
    const float* past_value = (const float*)d_in[4];
    const float* w_in       = (const float*)d_in[5];
    const float* b_in       = (const float*)d_in[6];
    const float* w_out      = (const float*)d_in[7];
    const float* b_out      = (const float*)d_in[8];

    float* out        = (float*)d_out;
    float* comb_key   = out + BB * DD;
    float* comb_value = comb_key + (size_t)BB * SP * DD;

    cudaFuncSetAttribute(k2_keyscores, cudaFuncAttributeMaxDynamicSharedMemorySize,
                         HH * DD * (int)sizeof(float));

    k0_qproj<<<64, 256>>>(query, w_in, b_in);
    k1_qkfold<<<dim3(16, 4), 256>>>(w_in);
    k2_keyscores<<<dim3(K2_NB, BB), 256, HH * DD * sizeof(float)>>>(past_key, key, comb_key);
    k3_stats<<<BB * HH, 256>>>();
    k4_valu<<<dim3(K4_NB, BB), 256>>>(past_value, value, comb_value);
    k4b_ured<<<256, 256>>>();
    k5_ctx<<<64, 256>>>(w_in, b_in);
    k6_out<<<64, 256>>>(w_out, b_out, out);
}

// round 16
// speedup vs baseline: 2.1597x; 1.5119x over previous
#include <cuda_runtime.h>
#include <math.h>

typedef unsigned long long u64;

#define BB 16
#define SS 4096
#define SP 4097
#define SPAD 4104              // padded scores row stride (multiple of 8 floats)
#define DD 1024
#define HH 16

// k2 persistent layout: 27 stripes x 16 batches = 432 CTAs (3 CTAs/SM @ 64KB smem)
#define K2_NB     27
#define K2_STRIPE 152
#define K2_ITERS  19           // 19 * 8 rows = 152

// k4 persistent layout: 18 stripes x 16 batches = 288 CTAs (2 CTAs/SM)
#define K4_NB     18
#define K4_STRIPE 228
#define K4_CH     128          // attn staging chunk

// ---- scratch (no allocations allowed) ----
__device__ float g_q[BB * DD];
__device__ float g_qk[BB * HH * DD];
__device__ __align__(16) float g_scores[(size_t)BB * HH * SPAD];
__device__ float g_smax[BB * HH];
__device__ float g_sinv[BB * HH];
__device__ float g_upart[(size_t)BB * K4_NB * HH * DD];
__device__ float g_u[BB * HH * DD];
__device__ float g_ctx[BB * DD];

// ---- packed dual-fp32 helpers (sm_100+) ----
__device__ __forceinline__ u64 fma2(u64 a, u64 b, u64 c) {
    u64 d;
    asm("fma.rn.f32x2 %0, %1, %2, %3;" : "=l"(d) : "l"(a), "l"(b), "l"(c));
    return d;
}
__device__ __forceinline__ float hsum2(u64 v) {
    float lo, hi;
    asm("mov.b64 {%0, %1}, %2;" : "=f"(lo), "=f"(hi) : "l"(v));
    return lo + hi;
}
__device__ __forceinline__ float wsum(float v) {
#pragma unroll
    for (int o = 16; o; o >>= 1) v += __shfl_xor_sync(0xffffffffu, v, o);
    return v;
}

// K0: warp-per-output GEMV. q[b,d] = 0.125*(query[b,:].w_in[d,:] + b_in[d])
// 16384 outputs, 8 warps/block, 2048 blocks.
__global__ void k0_qproj(const float* __restrict__ query,
                         const float* __restrict__ w_in,
                         const float* __restrict__ b_in) {
    int warp = threadIdx.x >> 5, lane = threadIdx.x & 31;
    int idx = blockIdx.x * 8 + warp;
    int b = idx & 15, d = idx >> 4;
    const float4* q = (const float4*)(query + b * DD);
    const float4* w = (const float4*)(w_in + (size_t)d * DD);
    float a = 0.f;
#pragma unroll
    for (int k = 0; k < 8; k++) {
        float4 wv = w[k * 32 + lane];
        float4 qv = q[k * 32 + lane];
        a += qv.x * wv.x + qv.y * wv.y + qv.z * wv.z + qv.w * wv.w;
    }
    a = wsum(a);
    if (lane == 0) g_q[b * DD + d] = (a + b_in[d]) * 0.125f;
}

// K1: qk[b,h,j] = sum_i q[b, h*64+i] * w_in[DD + h*64+i, j]
__global__ void k1_qkfold(const float* __restrict__ w_in) {
    __shared__ float qsm[BB * 64];
    int h = blockIdx.x;
    int jc = blockIdx.y;
    int t = threadIdx.x;
    for (int idx = t; idx < BB * 64; idx += 256) {
        int b = idx >> 6, i = idx & 63;
        qsm[idx] = g_q[b * DD + h * 64 + i];
    }
    __syncthreads();
    int j = jc * 256 + t;
    float acc[BB];
#pragma unroll
    for (int b = 0; b < BB; b++) acc[b] = 0.f;
    const float* w = w_in + (size_t)(DD + h * 64) * DD + j;
#pragma unroll 4
    for (int i = 0; i < 64; i++) {
        float wv = w[(size_t)i * DD];
#pragma unroll
        for (int b = 0; b < BB; b++) acc[b] += qsm[b * 64 + i] * wv;
    }
#pragma unroll
    for (int b = 0; b < BB; b++) g_qk[(b * HH + h) * DD + j] = acc[b];
}

// K2: persistent fused key-copy + scores, double-buffered k-loop (R4 geometry).
// Stores balanced: hhalf 0 stores row s0, hhalf 1 stores row s0+1 (streaming).
__global__ void __launch_bounds__(256, 3)
k2_keyscores(const float* __restrict__ past_key,
             const float* __restrict__ key,
             float* __restrict__ comb_key) {
    extern __shared__ float qk_sm[];  // HH*DD floats = 64 KB
    int b = blockIdx.y;
    int t = threadIdx.x;
    {
        const float4* src = (const float4*)(g_qk + (size_t)b * HH * DD);
        float4* dst = (float4*)qk_sm;
        for (int i = t; i < HH * DD / 4; i += 256) dst[i] = src[i];
    }
    __syncthreads();

    int warp = t >> 5, lane = t & 31;
    int hhalf = warp & 1;
    int rq = warp >> 1;
    int h0 = hhalf * 8;
    int stripe0 = blockIdx.x * K2_STRIPE;

    for (int it = 0; it < K2_ITERS; it++) {
        int s0 = stripe0 + it * 8 + rq * 2;   // warp-uniform
        if (s0 >= SP) break;
        bool valid1 = (s0 + 1) < SP;

        const float* src0 = (s0 < SS) ? past_key + ((size_t)b * SS + s0) * DD
                                      : key + (size_t)b * DD;
        const float* src1 = (s0 + 1 < SS) ? past_key + ((size_t)b * SS + s0 + 1) * DD
                                          : key + (size_t)b * DD;
        float* dst0 = comb_key + ((size_t)b * SP + s0) * DD;
        float* dst1 = comb_key + ((size_t)b * SP + (valid1 ? s0 + 1 : s0)) * DD;

        u64 acc[16];
#pragma unroll
        for (int i = 0; i < 16; i++) acc[i] = 0ull;

        int lj = lane * 4;
        ulonglong2 c0 = *(const ulonglong2*)(src0 + lj);
        ulonglong2 c1;
        if (valid1) c1 = *(const ulonglong2*)(src1 + lj);
        else { c1.x = 0ull; c1.y = 0ull; }

#pragma unroll
        for (int k = 0; k < 8; k++) {
            int jb = k * 128 + lj;
            ulonglong2 n0, n1;
            if (k < 7) {  // prefetch next chunk before compute
                n0 = *(const ulonglong2*)(src0 + jb + 128);
                if (valid1) n1 = *(const ulonglong2*)(src1 + jb + 128);
                else { n1.x = 0ull; n1.y = 0ull; }
            }
            // balanced streaming stores: hhalf0 -> row s0, hhalf1 -> row s0+1
            if (hhalf == 0) {
                __stcs((float4*)(dst0 + jb), *(const float4*)&c0);
            } else if (valid1) {
                __stcs((float4*)(dst1 + jb), *(const float4*)&c1);
            }
#pragma unroll
            for (int h8 = 0; h8 < 8; h8++) {
                ulonglong2 qv = *(const ulonglong2*)(qk_sm + (h0 + h8) * DD + jb);
                acc[h8 * 2 + 0] = fma2(qv.x, c0.x, acc[h8 * 2 + 0]);
                acc[h8 * 2 + 0] = fma2(qv.y, c0.y, acc[h8 * 2 + 0]);
                acc[h8 * 2 + 1] = fma2(qv.x, c1.x, acc[h8 * 2 + 1]);
                acc[h8 * 2 + 1] = fma2(qv.y, c1.y, acc[h8 * 2 + 1]);
            }
            if (k < 7) { c0 = n0; c1 = n1; }
        }
#pragma unroll
        for (int i = 0; i < 16; i++) {
            float v = hsum2(acc[i]);
            v += __shfl_xor_sync(0xffffffffu, v, 16);
            v += __shfl_xor_sync(0xffffffffu, v, 8);
            v += __shfl_xor_sync(0xffffffffu, v, 4);
            v += __shfl_xor_sync(0xffffffffu, v, 2);
            v += __shfl_xor_sync(0xffffffffu, v, 1);
            if (lane == 0) {
                int h8 = i >> 1, r = i & 1;
                int s = s0 + r;
                if (s < SP)
                    g_scores[((size_t)b * HH + h0 + h8) * SPAD + s] = v;
            }
        }
    }
}

// K3: one-pass online softmax stats per row -> (max, 1/sum).
// float4 loads (SPAD-aligned rows), 4-wide max tree.
__global__ void k3_stats() {
    __shared__ float red_m[8], red_s[8];
    int row = blockIdx.x;
    const float* sc = g_scores + (size_t)row * SPAD;
    int t = threadIdx.x;

    float m = -1e30f, s = 0.f;
#pragma unroll
    for (int k = 0; k < 4; k++) {
        float4 x = *(const float4*)(sc + (k * 256 + t) * 4);
        float mx = fmaxf(fmaxf(x.x, x.y), fmaxf(x.z, x.w));
        float nm = fmaxf(m, mx);
        s = s * __expf(m - nm)
          + __expf(x.x - nm) + __expf(x.y - nm)
          + __expf(x.z - nm) + __expf(x.w - nm);
        m = nm;
    }
    if (t == 0) {  // tail element 4096
        float x = sc[4096];
        float nm = fmaxf(m, x);
        s = s * __expf(m - nm) + __expf(x - nm);
        m = nm;
    }
#pragma unroll
    for (int o = 16; o; o >>= 1) {
        float om = __shfl_xor_sync(0xffffffffu, m, o);
        float os = __shfl_xor_sync(0xffffffffu, s, o);
        float nm = fmaxf(m, om);
        s = s * __expf(m - nm) + os * __expf(om - nm);
        m = nm;
    }
    if ((t & 31) == 0) { red_m[t >> 5] = m; red_s[t >> 5] = s; }
    __syncthreads();
    if (t == 0) {
        float M = red_m[0], S = red_s[0];
#pragma unroll
        for (int w = 1; w < 8; w++) {
            float nm = fmaxf(M, red_m[w]);
            S = S * __expf(M - nm) + red_s[w] * __expf(red_m[w] - nm);
            M = nm;
        }
        g_smax[row] = M;
        g_sinv[row] = 1.f / S;
    }
}

// K4: persistent fused value-copy + softmax-apply + u accumulation.
// f32x2 over j-pairs; attn staged DUPLICATED (float2{a,a}); 4-row batches with
// register prefetch. Value rows read __ldcs (read-once), comb stores __stcs.
__global__ void __launch_bounds__(256, 2)
k4_valu(const float* __restrict__ past_value,
        const float* __restrict__ value,
        float* __restrict__ comb_value) {
    __shared__ __align__(16) float2 attn2[HH][K4_CH];  // 16 KB
    int bx = blockIdx.x, b = blockIdx.y;
    int t = threadIdx.x;
    int j = t * 4;
    int s_begin = bx * K4_STRIPE;
    int rows_blk = SP - s_begin;
    if (rows_blk > K4_STRIPE) rows_blk = K4_STRIPE;

    u64 acc[HH][2];
#pragma unroll
    for (int h = 0; h < HH; h++) { acc[h][0] = 0ull; acc[h][1] = 0ull; }

    for (int cs = 0; cs < rows_blk; cs += K4_CH) {
        int rows_c = rows_blk - cs;
        if (rows_c > K4_CH) rows_c = K4_CH;
        __syncthreads();
        for (int idx = t; idx < HH * K4_CH; idx += 256) {
            int h = idx >> 7, si = idx & (K4_CH - 1);
            float a = 0.f;
            if (si < rows_c) {
                float x = g_scores[((size_t)b * HH + h) * SPAD + s_begin + cs + si];
                a = __expf(x - g_smax[b * HH + h]) * g_sinv[b * HH + h];
            }
            attn2[h][si] = make_float2(a, a);
        }
        __syncthreads();

        int base = s_begin + cs;
        int n_it = (rows_c + 3) >> 2;

        ulonglong2 cur[4];
#pragma unroll
        for (int r = 0; r < 4; r++) {
            int s = base + r; if (s > SP - 1) s = SP - 1;
            const float* p = (s < SS) ? past_value + ((size_t)b * SS + s) * DD + j
                                      : value + (size_t)b * DD + j;
            float4 tmp = __ldcs((const float4*)p);
            cur[r] = *(const ulonglong2*)&tmp;
        }

        for (int it = 0; it < n_it; it++) {
            int si0 = it * 4;
            ulonglong2 nxt[4];
            if (it + 1 < n_it) {
#pragma unroll
                for (int r = 0; r < 4; r++) {
                    int s = base + si0 + 4 + r; if (s > SP - 1) s = SP - 1;
                    const float* p = (s < SS) ? past_value + ((size_t)b * SS + s) * DD + j
                                              : value + (size_t)b * DD + j;
                    float4 tmp = __ldcs((const float4*)p);
                    nxt[r] = *(const ulonglong2*)&tmp;
                }
            }
#pragma unroll
            for (int r = 0; r < 4; r++) {
                int s = base + si0 + r;
                if (s < SP && (si0 + r) < rows_c)
                    __stcs((float4*)(comb_value + ((size_t)b * SP + s) * DD + j),
                           *(const float4*)&cur[r]);
            }
#pragma unroll
            for (int h = 0; h < HH; h++) {
                ulonglong2 a01 = *(const ulonglong2*)(&attn2[h][si0]);
                ulonglong2 a23 = *(const ulonglong2*)(&attn2[h][si0 + 2]);
                acc[h][0] = fma2(a01.x, cur[0].x, acc[h][0]);
                acc[h][1] = fma2(a01.x, cur[0].y, acc[h][1]);
                acc[h][0] = fma2(a01.y, cur[1].x, acc[h][0]);
                acc[h][1] = fma2(a01.y, cur[1].y, acc[h][1]);
                acc[h][0] = fma2(a23.x, cur[2].x, acc[h][0]);
                acc[h][1] = fma2(a23.x, cur[2].y, acc[h][1]);
                acc[h][0] = fma2(a23.y, cur[3].x, acc[h][0]);
                acc[h][1] = fma2(a23.y, cur[3].y, acc[h][1]);
            }
            if (it + 1 < n_it) {
#pragma unroll
                for (int r = 0; r < 4; r++) cur[r] = nxt[r];
            }
        }
    }

    // lanes of acc are adjacent j's — store directly, no horizontal reduce
    float* up = g_upart + ((size_t)(b * K4_NB + bx) * HH) * DD + j;
#pragma unroll
    for (int h = 0; h < HH; h++) {
        ulonglong2 o; o.x = acc[h][0]; o.y = acc[h][1];
        *(ulonglong2*)(up + (size_t)h * DD) = o;
    }
}

// K4b: u = sum over stripe-partials
__global__ void k4b_ured() {
    int idx = blockIdx.x * 256 + threadIdx.x;
    int e = idx * 4;
    int b = e >> 14;
    int rest = e & 16383;
    const float* up = g_upart + (size_t)b * K4_NB * HH * DD + rest;
    float4 s = make_float4(0.f, 0.f, 0.f, 0.f);
#pragma unroll
    for (int c = 0; c < K4_NB; c++) {
        float4 v = *(const float4*)(up + (size_t)c * HH * DD);
        s.x += v.x; s.y += v.y; s.z += v.z; s.w += v.w;
    }
    *(float4*)(g_u + e) = s;
}

// K5: warp-per-output. ctx[b,d] = u[b,d>>6,:].w_in[2D+d,:] + b_in[2D+d]
__global__ void k5_ctx(const float* __restrict__ w_in,
                       const float* __restrict__ b_in) {
    int warp = threadIdx.x >> 5, lane = threadIdx.x & 31;
    int idx = blockIdx.x * 8 + warp;
    int b = idx & 15, d = idx >> 4;
    int h = d >> 6;
    const float4* u = (const float4*)(g_u + (b * HH + h) * DD);
    const float4* w = (const float4*)(w_in + (size_t)(2 * DD + d) * DD);
    float a = 0.f;
#pragma unroll
    for (int k = 0; k < 8; k++) {
        float4 wv = w[k * 32 + lane];
        float4 uv = u[k * 32 + lane];
        a += uv.x * wv.x + uv.y * wv.y + uv.z * wv.z + uv.w * wv.w;
    }
    a = wsum(a);
    if (lane == 0) g_ctx[b * DD + d] = a + b_in[2 * DD + d];
}

// K6: warp-per-output. out[b,d] = ctx[b,:].w_out[d,:] + b_out[d]
__global__ void k6_out(const float* __restrict__ w_out,
                       const float* __restrict__ b_out,
                       float* __restrict__ out) {
    int warp = threadIdx.x >> 5, lane = threadIdx.x & 31;
    int idx = blockIdx.x * 8 + warp;
    int b = idx & 15, d = idx >> 4;
    const float4* c = (const float4*)(g_ctx + b * DD);
    const float4* w = (const float4*)(w_out + (size_t)d * DD);
    float a = 0.f;
#pragma unroll
    for (int k = 0; k < 8; k++) {
        float4 wv = w[k * 32 + lane];
        float4 cv = c[k * 32 + lane];
        a += cv.x * wv.x + cv.y * wv.y + cv.z * wv.z + cv.w * wv.w;
    }
    a = wsum(a);
    if (lane == 0) out[b * DD + d] = a + b_out[d];
}

extern "C" void kernel_launch(void* const* d_in, const int* in_sizes, int n_in,
                              void* d_out, int out_size) {
    const float* query      = (const float*)d_in[0];
    const float* key        = (const float*)d_in[1];
    const float* value      = (const float*)d_in[2];
    const float* past_key   = (const float*)d_in[3];
    const float* past_value = (const float*)d_in[4];
    const float* w_in       = (const float*)d_in[5];
    const float* b_in       = (const float*)d_in[6];
    const float* w_out      = (const float*)d_in[7];
    const float* b_out      = (const float*)d_in[8];

    float* out        = (float*)d_out;
    float* comb_key   = out + BB * DD;
    float* comb_value = comb_key + (size_t)BB * SP * DD;

    cudaFuncSetAttribute(k2_keyscores, cudaFuncAttributeMaxDynamicSharedMemorySize,
                         HH * DD * (int)sizeof(float));

    k0_qproj<<<2048, 256>>>(query, w_in, b_in);
    k1_qkfold<<<dim3(16, 4), 256>>>(w_in);
    k2_keyscores<<<dim3(K2_NB, BB), 256, HH * DD * sizeof(float)>>>(past_key, key, comb_key);
    k3_stats<<<BB * HH, 256>>>();
    k4_valu<<<dim3(K4_NB, BB), 256>>>(past_value, value, comb_value);
    k4b_ured<<<256, 256>>>();
    k5_ctx<<<2048, 256>>>(w_in, b_in);
    k6_out<<<2048, 256>>>(w_out, b_out, out);
}